// round 3
// baseline (speedup 1.0000x reference)
#include <cuda_runtime.h>
#include <math.h>

#define L_ 4
#define B_ 8
#define PH 37
#define PW 37
#define P_ 1369
#define D_ 1024
#define J_ 768
#define SLAB (P_*D_)           /* 1401856 */
#define TOT (L_*B_*SLAB)       /* 44859392 */
#define NPAIR 28
#define HOUT 518
#define WOUT 518

// ------------------- static device scratch (no allocations) -------------------
__device__ float g_feats[TOT];                 // layer-normalized features
__device__ float g_tmp[TOT];                   // horizontal box-filter temp
__device__ float g_rf[TOT];                    // filtered + L2-normalized
__device__ unsigned g_maxdot[L_*B_*B_*P_];     // encoded max dot per (l,i,j,p)
__device__ float g_scores[B_*P_];              // accumulated scores (sum over l,r)
__device__ float g_part[L_*B_*64*2];           // LN partial sums
__device__ float g_musig[L_*B_*2];             // LN mean / rsigma
__device__ float g_img[B_];                    // per-image max score

__constant__ int c_pi[NPAIR] = {0,0,0,0,0,0,0,1,1,1,1,1,1,2,2,2,2,2,3,3,3,3,4,4,4,5,5,6};
__constant__ int c_pj[NPAIR] = {1,2,3,4,5,6,7,2,3,4,5,6,7,3,4,5,6,7,4,5,6,7,5,6,7,6,7,7};

// order-preserving float<->uint encoding so atomicMax(unsigned) == float max
__device__ __forceinline__ unsigned fenc(float f){
    unsigned u = __float_as_uint(f);
    return (u & 0x80000000u) ? ~u : (u | 0x80000000u);
}
__device__ __forceinline__ float fdec(unsigned u){
    return (u & 0x80000000u) ? __uint_as_float(u & 0x7fffffffu) : __uint_as_float(~u);
}

// ------------------- layer norm over (P,D) per (l,b) -------------------
__global__ void ln_part(const float* __restrict__ x){
    int slab  = blockIdx.x >> 6;
    int chunk = blockIdx.x & 63;
    const int n = SLAB / 64;  // 21904
    const float* p = x + (size_t)slab*SLAB + (size_t)chunk*n;
    float s = 0.f, ss = 0.f;
    for (int i = threadIdx.x; i < n; i += 256){ float v = p[i]; s += v; ss += v*v; }
    __shared__ float sh[256], sh2[256];
    sh[threadIdx.x] = s; sh2[threadIdx.x] = ss; __syncthreads();
    for (int o = 128; o > 0; o >>= 1){
        if (threadIdx.x < o){ sh[threadIdx.x] += sh[threadIdx.x+o]; sh2[threadIdx.x] += sh2[threadIdx.x+o]; }
        __syncthreads();
    }
    if (threadIdx.x == 0){ g_part[blockIdx.x*2] = sh[0]; g_part[blockIdx.x*2+1] = sh2[0]; }
}

__global__ void ln_stats(){
    int slab = blockIdx.x;
    __shared__ float sh[64], sh2[64];
    sh[threadIdx.x]  = g_part[(slab*64 + threadIdx.x)*2];
    sh2[threadIdx.x] = g_part[(slab*64 + threadIdx.x)*2 + 1];
    __syncthreads();
    for (int o = 32; o > 0; o >>= 1){
        if (threadIdx.x < o){ sh[threadIdx.x] += sh[threadIdx.x+o]; sh2[threadIdx.x] += sh2[threadIdx.x+o]; }
        __syncthreads();
    }
    if (threadIdx.x == 0){
        float mu  = sh[0]  / (float)SLAB;
        float var = sh2[0] / (float)SLAB - mu*mu;
        g_musig[slab*2]   = mu;
        g_musig[slab*2+1] = rsqrtf(var + 1e-5f);
    }
}

__global__ void ln_apply(const float* __restrict__ x){
    int e = blockIdx.x*256 + threadIdx.x;           // < SLAB (exact multiple)
    int slab = blockIdx.y;
    size_t idx = (size_t)slab*SLAB + e;
    float mu = g_musig[slab*2], rs = g_musig[slab*2+1];
    g_feats[idx] = (x[idx] - mu) * rs;
}

// ------------------- separable box filter + row L2 normalize -------------------
__global__ void box_h(int r){
    int lb = blockIdx.y;
    int e = blockIdx.x*256 + threadIdx.x;           // < SLAB
    int d = e & (D_-1);
    int p = e >> 10;
    int h = p / PW, w = p % PW;
    int pad = r >> 1;
    const float* src = g_feats + (size_t)lb*SLAB;
    float s = 0.f;
    for (int dw = -pad; dw <= pad; dw++){
        int ww = w + dw;
        if (ww >= 0 && ww < PW) s += src[(size_t)(h*PW + ww)*D_ + d];
    }
    g_tmp[(size_t)lb*SLAB + e] = s;
}

__global__ void box_v_norm(int r, int fromTmp, float scale){
    int row = blockIdx.x;                 // (l*B+b)*P + p
    int lb = row / P_;
    int p  = row % P_;
    int h = p / PW, w = p % PW;
    int pad = r >> 1;
    const float* src = (fromTmp ? g_tmp : g_feats) + (size_t)lb*SLAB;
    float vals[4];
    float ssq = 0.f;
    #pragma unroll
    for (int i = 0; i < 4; i++){
        int d = threadIdx.x + i*256;
        float s = 0.f;
        for (int dh = -pad; dh <= pad; dh++){
            int hh = h + dh;
            if (hh >= 0 && hh < PH) s += src[(size_t)(hh*PW + w)*D_ + d];
        }
        s *= scale;
        vals[i] = s;
        ssq += s*s;
    }
    __shared__ float sh[256];
    sh[threadIdx.x] = ssq; __syncthreads();
    for (int o = 128; o > 0; o >>= 1){
        if (threadIdx.x < o) sh[threadIdx.x] += sh[threadIdx.x+o];
        __syncthreads();
    }
    float inv = 1.0f / sqrtf(sh[0]);
    float* dst = g_rf + (size_t)row*D_;
    #pragma unroll
    for (int i = 0; i < 4; i++) dst[threadIdx.x + i*256] = vals[i]*inv;
}

// ------------------- clears -------------------
__global__ void clear_maxdot(){
    int i = blockIdx.x*256 + threadIdx.x;
    if (i < L_*B_*B_*P_) g_maxdot[i] = 0u;
}
__global__ void clear_scores(){
    int i = blockIdx.x*256 + threadIdx.x;
    if (i < B_*P_) g_scores[i] = 0.f;
}

// ------------------- fused pair GEMM + row/col max -------------------
// C[p,q] = <rf[l,i,p,:], rf[l,j,q,:]>; rowmax -> maxdot[l,i,j,p]; colmax -> maxdot[l,j,i,q]
__launch_bounds__(256)
__global__ void gemm_max(){
    const int l  = blockIdx.z / NPAIR;
    const int pi = blockIdx.z % NPAIR;
    const int im = c_pi[pi], jm = c_pj[pi];
    const float* __restrict__ A  = g_rf + (size_t)(l*B_ + im)*SLAB;
    const float* __restrict__ Bp = g_rf + (size_t)(l*B_ + jm)*SLAB;
    const int m0 = blockIdx.y*128, n0 = blockIdx.x*128;

    __shared__ __align__(16) float As[8][132];
    __shared__ __align__(16) float Bs[8][132];
    __shared__ unsigned red[256];   // [0..127]=row max enc, [128..255]=col max enc

    float c[8][8];
    #pragma unroll
    for (int a = 0; a < 8; a++)
        #pragma unroll
        for (int b = 0; b < 8; b++) c[a][b] = 0.f;

    const int tid = threadIdx.x;
    const int lrow = tid >> 1;
    const int lk   = (tid & 1) * 4;
    const int ty = tid >> 4, tx = tid & 15;
    const int arow = m0 + lrow, brow = n0 + lrow;
    const bool av = arow < P_, bv = brow < P_;
    const float* ap = A  + (size_t)(av ? arow : 0)*D_ + lk;
    const float* bp = Bp + (size_t)(bv ? brow : 0)*D_ + lk;

    for (int k0 = 0; k0 < D_; k0 += 8){
        float4 a4 = av ? *(const float4*)(ap + k0) : make_float4(0.f,0.f,0.f,0.f);
        float4 b4 = bv ? *(const float4*)(bp + k0) : make_float4(0.f,0.f,0.f,0.f);
        __syncthreads();
        As[lk+0][lrow] = a4.x; As[lk+1][lrow] = a4.y; As[lk+2][lrow] = a4.z; As[lk+3][lrow] = a4.w;
        Bs[lk+0][lrow] = b4.x; Bs[lk+1][lrow] = b4.y; Bs[lk+2][lrow] = b4.z; Bs[lk+3][lrow] = b4.w;
        __syncthreads();
        #pragma unroll
        for (int k = 0; k < 8; k++){
            float ar[8], br[8];
            *(float4*)&ar[0] = *(const float4*)&As[k][ty*4];
            *(float4*)&ar[4] = *(const float4*)&As[k][ty*4 + 64];
            *(float4*)&br[0] = *(const float4*)&Bs[k][tx*4];
            *(float4*)&br[4] = *(const float4*)&Bs[k][tx*4 + 64];
            #pragma unroll
            for (int a = 0; a < 8; a++)
                #pragma unroll
                for (int b = 0; b < 8; b++)
                    c[a][b] = fmaf(ar[a], br[b], c[a][b]);
        }
    }

    int rIdx[8], cIdx[8];
    #pragma unroll
    for (int a = 0; a < 8; a++) rIdx[a] = ty*4 + (a < 4 ? a : 60 + a);
    #pragma unroll
    for (int b = 0; b < 8; b++) cIdx[b] = tx*4 + (b < 4 ? b : 60 + b);

    __syncthreads();
    red[tid] = 0u;
    __syncthreads();

    #pragma unroll
    for (int a = 0; a < 8; a++){
        if (m0 + rIdx[a] >= P_) continue;
        float mx = -1e30f; bool any = false;
        #pragma unroll
        for (int b = 0; b < 8; b++){
            if (n0 + cIdx[b] < P_){ mx = fmaxf(mx, c[a][b]); any = true; }
        }
        if (any) atomicMax(&red[rIdx[a]], fenc(mx));
    }
    #pragma unroll
    for (int b = 0; b < 8; b++){
        if (n0 + cIdx[b] >= P_) continue;
        float mx = -1e30f; bool any = false;
        #pragma unroll
        for (int a = 0; a < 8; a++){
            if (m0 + rIdx[a] < P_){ mx = fmaxf(mx, c[a][b]); any = true; }
        }
        if (any) atomicMax(&red[128 + cIdx[b]], fenc(mx));
    }
    __syncthreads();

    if (tid < 128){
        int gm = m0 + tid;
        if (gm < P_ && red[tid])
            atomicMax(&g_maxdot[(((size_t)l*B_ + im)*B_ + jm)*P_ + gm], red[tid]);
    } else {
        int t = tid - 128;
        int gn = n0 + t;
        if (gn < P_ && red[tid])
            atomicMax(&g_maxdot[(((size_t)l*B_ + jm)*B_ + im)*P_ + gn], red[tid]);
    }
}

// ------------------- top-2 over j, distance, accumulate over l -------------------
__global__ void score_accum(){
    int idx = blockIdx.x*256 + threadIdx.x;
    if (idx >= B_*P_) return;
    int i = idx / P_, p = idx % P_;
    float acc = 0.f;
    for (int l = 0; l < L_; l++){
        const unsigned* md = &g_maxdot[(((size_t)l*B_ + i)*B_)*P_ + p];
        float b1 = -1e30f, b2 = -1e30f;
        #pragma unroll
        for (int j = 0; j < B_; j++){
            if (j == i) continue;
            float v = fdec(md[(size_t)j*P_]);
            if (v > b1){ b2 = b1; b1 = v; } else if (v > b2){ b2 = v; }
        }
        float d1 = sqrtf(fmaxf(2.f - 2.f*b1, 1e-12f));
        float d2 = sqrtf(fmaxf(2.f - 2.f*b2, 1e-12f));
        acc += 0.5f*(d1 + d2);
    }
    g_scores[idx] += acc;
}

// ------------------- image max score -------------------
__global__ void img_max(){
    int b = blockIdx.x;
    float mx = -1e30f;
    for (int p = threadIdx.x; p < P_; p += 256) mx = fmaxf(mx, g_scores[b*P_ + p]);
    __shared__ float sh[256];
    sh[threadIdx.x] = mx; __syncthreads();
    for (int o = 128; o > 0; o >>= 1){
        if (threadIdx.x < o) sh[threadIdx.x] = fmaxf(sh[threadIdx.x], sh[threadIdx.x+o]);
        __syncthreads();
    }
    if (threadIdx.x == 0) g_img[b] = sh[0]*(1.f/12.f);
}

// ------------------- RsCIN head: cls sim + topk reweight -------------------
__global__ void final_kernel(const float* __restrict__ cls, float* __restrict__ out){
    __shared__ float sim[8][8];
    __shared__ float nrm[8];
    int t = threadIdx.x; // 64 threads
    if (t < 8){
        float s = 0.f; const float* c = cls + t*J_;
        for (int k = 0; k < J_; k++) s += c[k]*c[k];
        nrm[t] = sqrtf(s);
    }
    __syncthreads();
    {
        int i = t >> 3, j = t & 7;
        float s = 0.f;
        const float* a = cls + i*J_;
        const float* b = cls + j*J_;
        for (int k = 0; k < J_; k++) s += a[k]*b[k];
        sim[i][j] = s / (nrm[i]*nrm[j]);
    }
    __syncthreads();
    if (t < 8){
        float row[8];
        #pragma unroll
        for (int j = 0; j < 8; j++) row[j] = sim[t][j];
        bool used[8] = {false,false,false,false,false,false,false,false};
        float acc = 0.f, svals = 0.f, snum = 0.f;
        for (int k = 1; k <= 3; k++){
            int bi = 0; float bv = -1e30f;
            for (int j = 0; j < 8; j++)
                if (!used[j] && row[j] > bv){ bv = row[j]; bi = j; }
            used[bi] = true;
            svals += bv; snum += bv * g_img[bi];
            acc += snum / svals;
        }
        out[t] = acc * (1.f/3.f);
    }
}

// ------------------- bilinear upsample 37x37 -> 518x518 -------------------
__global__ void pixel_kernel(float* __restrict__ out){
    int idx = blockIdx.x*256 + threadIdx.x;
    if (idx >= B_*HOUT*WOUT) return;
    int b = idx / (HOUT*WOUT);
    int rem = idx % (HOUT*WOUT);
    int y = rem / WOUT, x = rem % WOUT;
    const float sc = (float)(36.0/517.0);
    float py = (float)y * sc, px = (float)x * sc;
    int i0 = min(max((int)floorf(py), 0), 36); int i1 = min(i0 + 1, 36); float wy = py - (float)i0;
    int j0 = min(max((int)floorf(px), 0), 36); int j1 = min(j0 + 1, 36); float wx = px - (float)j0;
    const float* s = g_scores + (size_t)b*P_;
    const float m = 1.f/12.f;
    float v00 = s[i0*PW + j0]*m, v01 = s[i0*PW + j1]*m;
    float v10 = s[i1*PW + j0]*m, v11 = s[i1*PW + j1]*m;
    out[idx] = (1.f - wy)*((1.f - wx)*v00 + wx*v01) + wy*((1.f - wx)*v10 + wx*v11);
}

// ------------------- launch -------------------
extern "C" void kernel_launch(void* const* d_in, const int* in_sizes, int n_in,
                              void* d_out, int out_size){
    const float* feats = (const float*)d_in[0];
    const float* cls   = (const float*)d_in[1];
    float* out = (float*)d_out;

    ln_part<<<L_*B_*64, 256>>>(feats);
    ln_stats<<<L_*B_, 64>>>();
    ln_apply<<<dim3(SLAB/256, L_*B_), 256>>>(feats);

    clear_scores<<<(B_*P_ + 255)/256, 256>>>();

    const int rlist[3] = {1, 3, 5};
    for (int ri = 0; ri < 3; ri++){
        int r = rlist[ri];
        if (r > 1) box_h<<<dim3(SLAB/256, L_*B_), 256>>>(r);
        box_v_norm<<<L_*B_*P_, 256>>>(r, (r > 1) ? 1 : 0, 1.0f/(float)(r*r));
        clear_maxdot<<<(L_*B_*B_*P_ + 255)/256, 256>>>();
        gemm_max<<<dim3(11, 11, L_*NPAIR), 256>>>();
        score_accum<<<(B_*P_ + 255)/256, 256>>>();
    }

    img_max<<<B_, 256>>>();
    final_kernel<<<1, 64>>>(cls, out);
    pixel_kernel<<<(B_*HOUT*WOUT + 255)/256, 256>>>(out + 8);
}

// round 4
// speedup vs baseline: 1.0004x; 1.0004x over previous
#include <cuda_runtime.h>
#include <math.h>

#define L_ 4
#define B_ 8
#define PH 37
#define PW 37
#define P_ 1369
#define D_ 1024
#define J_ 768
#define SLAB (P_*D_)           /* 1401856 */
#define TOT (L_*B_*SLAB)       /* 44859392 */
#define NPAIR 28
#define HOUT 518
#define WOUT 518

// ------------------- static device scratch (no allocations) -------------------
__device__ float g_feats[TOT];                 // layer-normalized features
__device__ float g_tmp[TOT];                   // horizontal box-filter temp
__device__ float g_rf[TOT];                    // filtered + L2-normalized
__device__ unsigned g_maxdot[L_*B_*B_*P_];     // encoded max dot per (l,i,j,p)
__device__ float g_scores[B_*P_];              // accumulated scores (sum over l,r)
__device__ float g_part[L_*B_*64*2];           // LN partial sums
__device__ float g_musig[L_*B_*2];             // LN mean / rsigma
__device__ float g_img[B_];                    // per-image max score

__constant__ int c_pi[NPAIR] = {0,0,0,0,0,0,0,1,1,1,1,1,1,2,2,2,2,2,3,3,3,3,4,4,4,5,5,6};
__constant__ int c_pj[NPAIR] = {1,2,3,4,5,6,7,2,3,4,5,6,7,3,4,5,6,7,4,5,6,7,5,6,7,6,7,7};

// order-preserving float<->uint encoding so atomicMax(unsigned) == float max
__device__ __forceinline__ unsigned fenc(float f){
    unsigned u = __float_as_uint(f);
    return (u & 0x80000000u) ? ~u : (u | 0x80000000u);
}
__device__ __forceinline__ float fdec(unsigned u){
    return (u & 0x80000000u) ? __uint_as_float(u & 0x7fffffffu) : __uint_as_float(~u);
}

// ------------------- layer norm over (P,D) per (l,b) -------------------
__global__ void ln_part(const float* __restrict__ x){
    int slab  = blockIdx.x >> 6;
    int chunk = blockIdx.x & 63;
    const int n = SLAB / 64;  // 21904
    const float* p = x + (size_t)slab*SLAB + (size_t)chunk*n;
    float s = 0.f, ss = 0.f;
    for (int i = threadIdx.x; i < n; i += 256){ float v = p[i]; s += v; ss += v*v; }
    __shared__ float sh[256], sh2[256];
    sh[threadIdx.x] = s; sh2[threadIdx.x] = ss; __syncthreads();
    for (int o = 128; o > 0; o >>= 1){
        if (threadIdx.x < o){ sh[threadIdx.x] += sh[threadIdx.x+o]; sh2[threadIdx.x] += sh2[threadIdx.x+o]; }
        __syncthreads();
    }
    if (threadIdx.x == 0){ g_part[blockIdx.x*2] = sh[0]; g_part[blockIdx.x*2+1] = sh2[0]; }
}

__global__ void ln_stats(){
    int slab = blockIdx.x;
    __shared__ float sh[64], sh2[64];
    sh[threadIdx.x]  = g_part[(slab*64 + threadIdx.x)*2];
    sh2[threadIdx.x] = g_part[(slab*64 + threadIdx.x)*2 + 1];
    __syncthreads();
    for (int o = 32; o > 0; o >>= 1){
        if (threadIdx.x < o){ sh[threadIdx.x] += sh[threadIdx.x+o]; sh2[threadIdx.x] += sh2[threadIdx.x+o]; }
        __syncthreads();
    }
    if (threadIdx.x == 0){
        float mu  = sh[0]  / (float)SLAB;
        float var = sh2[0] / (float)SLAB - mu*mu;
        g_musig[slab*2]   = mu;
        g_musig[slab*2+1] = rsqrtf(var + 1e-5f);
    }
}

__global__ void ln_apply(const float* __restrict__ x){
    int e = blockIdx.x*256 + threadIdx.x;           // < SLAB (exact multiple)
    int slab = blockIdx.y;
    size_t idx = (size_t)slab*SLAB + e;
    float mu = g_musig[slab*2], rs = g_musig[slab*2+1];
    g_feats[idx] = (x[idx] - mu) * rs;
}

// ------------------- separable box filter + row L2 normalize -------------------
__global__ void box_h(int r){
    int lb = blockIdx.y;
    int e = blockIdx.x*256 + threadIdx.x;           // < SLAB
    int d = e & (D_-1);
    int p = e >> 10;
    int h = p / PW, w = p % PW;
    int pad = r >> 1;
    const float* src = g_feats + (size_t)lb*SLAB;
    float s = 0.f;
    for (int dw = -pad; dw <= pad; dw++){
        int ww = w + dw;
        if (ww >= 0 && ww < PW) s += src[(size_t)(h*PW + ww)*D_ + d];
    }
    g_tmp[(size_t)lb*SLAB + e] = s;
}

__global__ void box_v_norm(int r, int fromTmp, float scale){
    int row = blockIdx.x;                 // (l*B+b)*P + p
    int lb = row / P_;
    int p  = row % P_;
    int h = p / PW, w = p % PW;
    int pad = r >> 1;
    const float* src = (fromTmp ? g_tmp : g_feats) + (size_t)lb*SLAB;
    float vals[4];
    float ssq = 0.f;
    #pragma unroll
    for (int i = 0; i < 4; i++){
        int d = threadIdx.x + i*256;
        float s = 0.f;
        for (int dh = -pad; dh <= pad; dh++){
            int hh = h + dh;
            if (hh >= 0 && hh < PH) s += src[(size_t)(hh*PW + w)*D_ + d];
        }
        s *= scale;
        vals[i] = s;
        ssq += s*s;
    }
    __shared__ float sh[256];
    sh[threadIdx.x] = ssq; __syncthreads();
    for (int o = 128; o > 0; o >>= 1){
        if (threadIdx.x < o) sh[threadIdx.x] += sh[threadIdx.x+o];
        __syncthreads();
    }
    float inv = 1.0f / sqrtf(sh[0]);
    float* dst = g_rf + (size_t)row*D_;
    #pragma unroll
    for (int i = 0; i < 4; i++) dst[threadIdx.x + i*256] = vals[i]*inv;
}

// ------------------- clears -------------------
__global__ void clear_maxdot(){
    int i = blockIdx.x*256 + threadIdx.x;
    if (i < L_*B_*B_*P_) g_maxdot[i] = 0u;
}
__global__ void clear_scores(){
    int i = blockIdx.x*256 + threadIdx.x;
    if (i < B_*P_) g_scores[i] = 0.f;
}

// ------------------- fused pair GEMM + row/col max -------------------
// C[p,q] = <rf[l,i,p,:], rf[l,j,q,:]>; rowmax -> maxdot[l,i,j,p]; colmax -> maxdot[l,j,i,q]
__launch_bounds__(256)
__global__ void gemm_max(){
    const int l  = blockIdx.z / NPAIR;
    const int pi = blockIdx.z % NPAIR;
    const int im = c_pi[pi], jm = c_pj[pi];
    const float* __restrict__ A  = g_rf + (size_t)(l*B_ + im)*SLAB;
    const float* __restrict__ Bp = g_rf + (size_t)(l*B_ + jm)*SLAB;
    const int m0 = blockIdx.y*128, n0 = blockIdx.x*128;

    __shared__ __align__(16) float As[8][132];
    __shared__ __align__(16) float Bs[8][132];
    __shared__ unsigned red[256];   // [0..127]=row max enc, [128..255]=col max enc

    float c[8][8];
    #pragma unroll
    for (int a = 0; a < 8; a++)
        #pragma unroll
        for (int b = 0; b < 8; b++) c[a][b] = 0.f;

    const int tid = threadIdx.x;
    const int lrow = tid >> 1;
    const int lk   = (tid & 1) * 4;
    const int ty = tid >> 4, tx = tid & 15;
    const int arow = m0 + lrow, brow = n0 + lrow;
    const bool av = arow < P_, bv = brow < P_;
    const float* ap = A  + (size_t)(av ? arow : 0)*D_ + lk;
    const float* bp = Bp + (size_t)(bv ? brow : 0)*D_ + lk;

    for (int k0 = 0; k0 < D_; k0 += 8){
        float4 a4 = av ? *(const float4*)(ap + k0) : make_float4(0.f,0.f,0.f,0.f);
        float4 b4 = bv ? *(const float4*)(bp + k0) : make_float4(0.f,0.f,0.f,0.f);
        __syncthreads();
        As[lk+0][lrow] = a4.x; As[lk+1][lrow] = a4.y; As[lk+2][lrow] = a4.z; As[lk+3][lrow] = a4.w;
        Bs[lk+0][lrow] = b4.x; Bs[lk+1][lrow] = b4.y; Bs[lk+2][lrow] = b4.z; Bs[lk+3][lrow] = b4.w;
        __syncthreads();
        #pragma unroll
        for (int k = 0; k < 8; k++){
            float ar[8], br[8];
            *(float4*)&ar[0] = *(const float4*)&As[k][ty*4];
            *(float4*)&ar[4] = *(const float4*)&As[k][ty*4 + 64];
            *(float4*)&br[0] = *(const float4*)&Bs[k][tx*4];
            *(float4*)&br[4] = *(const float4*)&Bs[k][tx*4 + 64];
            #pragma unroll
            for (int a = 0; a < 8; a++)
                #pragma unroll
                for (int b = 0; b < 8; b++)
                    c[a][b] = fmaf(ar[a], br[b], c[a][b]);
        }
    }

    int rIdx[8], cIdx[8];
    #pragma unroll
    for (int a = 0; a < 8; a++) rIdx[a] = ty*4 + (a < 4 ? a : 60 + a);
    #pragma unroll
    for (int b = 0; b < 8; b++) cIdx[b] = tx*4 + (b < 4 ? b : 60 + b);

    __syncthreads();
    red[tid] = 0u;
    __syncthreads();

    #pragma unroll
    for (int a = 0; a < 8; a++){
        if (m0 + rIdx[a] >= P_) continue;
        float mx = -1e30f; bool any = false;
        #pragma unroll
        for (int b = 0; b < 8; b++){
            if (n0 + cIdx[b] < P_){ mx = fmaxf(mx, c[a][b]); any = true; }
        }
        if (any) atomicMax(&red[rIdx[a]], fenc(mx));
    }
    #pragma unroll
    for (int b = 0; b < 8; b++){
        if (n0 + cIdx[b] >= P_) continue;
        float mx = -1e30f; bool any = false;
        #pragma unroll
        for (int a = 0; a < 8; a++){
            if (m0 + rIdx[a] < P_){ mx = fmaxf(mx, c[a][b]); any = true; }
        }
        if (any) atomicMax(&red[128 + cIdx[b]], fenc(mx));
    }
    __syncthreads();

    if (tid < 128){
        int gm = m0 + tid;
        if (gm < P_ && red[tid])
            atomicMax(&g_maxdot[(((size_t)l*B_ + im)*B_ + jm)*P_ + gm], red[tid]);
    } else {
        int t = tid - 128;
        int gn = n0 + t;
        if (gn < P_ && red[tid])
            atomicMax(&g_maxdot[(((size_t)l*B_ + jm)*B_ + im)*P_ + gn], red[tid]);
    }
}

// ------------------- top-2 over j, distance, accumulate over l -------------------
__global__ void score_accum(){
    int idx = blockIdx.x*256 + threadIdx.x;
    if (idx >= B_*P_) return;
    int i = idx / P_, p = idx % P_;
    float acc = 0.f;
    for (int l = 0; l < L_; l++){
        const unsigned* md = &g_maxdot[(((size_t)l*B_ + i)*B_)*P_ + p];
        float b1 = -1e30f, b2 = -1e30f;
        #pragma unroll
        for (int j = 0; j < B_; j++){
            if (j == i) continue;
            float v = fdec(md[(size_t)j*P_]);
            if (v > b1){ b2 = b1; b1 = v; } else if (v > b2){ b2 = v; }
        }
        float d1 = sqrtf(fmaxf(2.f - 2.f*b1, 1e-12f));
        float d2 = sqrtf(fmaxf(2.f - 2.f*b2, 1e-12f));
        acc += 0.5f*(d1 + d2);
    }
    g_scores[idx] += acc;
}

// ------------------- image max score -------------------
__global__ void img_max(){
    int b = blockIdx.x;
    float mx = -1e30f;
    for (int p = threadIdx.x; p < P_; p += 256) mx = fmaxf(mx, g_scores[b*P_ + p]);
    __shared__ float sh[256];
    sh[threadIdx.x] = mx; __syncthreads();
    for (int o = 128; o > 0; o >>= 1){
        if (threadIdx.x < o) sh[threadIdx.x] = fmaxf(sh[threadIdx.x], sh[threadIdx.x+o]);
        __syncthreads();
    }
    if (threadIdx.x == 0) g_img[b] = sh[0]*(1.f/12.f);
}

// ------------------- RsCIN head: cls sim + topk reweight -------------------
__global__ void final_kernel(const float* __restrict__ cls, float* __restrict__ out){
    __shared__ float sim[8][8];
    __shared__ float nrm[8];
    int t = threadIdx.x; // 64 threads
    if (t < 8){
        float s = 0.f; const float* c = cls + t*J_;
        for (int k = 0; k < J_; k++) s += c[k]*c[k];
        nrm[t] = sqrtf(s);
    }
    __syncthreads();
    {
        int i = t >> 3, j = t & 7;
        float s = 0.f;
        const float* a = cls + i*J_;
        const float* b = cls + j*J_;
        for (int k = 0; k < J_; k++) s += a[k]*b[k];
        sim[i][j] = s / (nrm[i]*nrm[j]);
    }
    __syncthreads();
    if (t < 8){
        float row[8];
        #pragma unroll
        for (int j = 0; j < 8; j++) row[j] = sim[t][j];
        bool used[8] = {false,false,false,false,false,false,false,false};
        float acc = 0.f, svals = 0.f, snum = 0.f;
        for (int k = 1; k <= 3; k++){
            int bi = 0; float bv = -1e30f;
            for (int j = 0; j < 8; j++)
                if (!used[j] && row[j] > bv){ bv = row[j]; bi = j; }
            used[bi] = true;
            svals += bv; snum += bv * g_img[bi];
            acc += snum / svals;
        }
        out[t] = acc * (1.f/3.f);
    }
}

// ------------------- bilinear upsample 37x37 -> 518x518 -------------------
__global__ void pixel_kernel(float* __restrict__ out){
    int idx = blockIdx.x*256 + threadIdx.x;
    if (idx >= B_*HOUT*WOUT) return;
    int b = idx / (HOUT*WOUT);
    int rem = idx % (HOUT*WOUT);
    int y = rem / WOUT, x = rem % WOUT;
    const float sc = (float)(36.0/517.0);
    float py = (float)y * sc, px = (float)x * sc;
    int i0 = min(max((int)floorf(py), 0), 36); int i1 = min(i0 + 1, 36); float wy = py - (float)i0;
    int j0 = min(max((int)floorf(px), 0), 36); int j1 = min(j0 + 1, 36); float wx = px - (float)j0;
    const float* s = g_scores + (size_t)b*P_;
    const float m = 1.f/12.f;
    float v00 = s[i0*PW + j0]*m, v01 = s[i0*PW + j1]*m;
    float v10 = s[i1*PW + j0]*m, v11 = s[i1*PW + j1]*m;
    out[idx] = (1.f - wy)*((1.f - wx)*v00 + wx*v01) + wy*((1.f - wx)*v10 + wx*v11);
}

// ------------------- launch -------------------
extern "C" void kernel_launch(void* const* d_in, const int* in_sizes, int n_in,
                              void* d_out, int out_size){
    const float* feats = (const float*)d_in[0];
    const float* cls   = (const float*)d_in[1];
    float* out = (float*)d_out;

    ln_part<<<L_*B_*64, 256>>>(feats);
    ln_stats<<<L_*B_, 64>>>();
    ln_apply<<<dim3(SLAB/256, L_*B_), 256>>>(feats);

    clear_scores<<<(B_*P_ + 255)/256, 256>>>();

    const int rlist[3] = {1, 3, 5};
    for (int ri = 0; ri < 3; ri++){
        int r = rlist[ri];
        if (r > 1) box_h<<<dim3(SLAB/256, L_*B_), 256>>>(r);
        box_v_norm<<<L_*B_*P_, 256>>>(r, (r > 1) ? 1 : 0, 1.0f/(float)(r*r));
        clear_maxdot<<<(L_*B_*B_*P_ + 255)/256, 256>>>();
        gemm_max<<<dim3(11, 11, L_*NPAIR), 256>>>();
        score_accum<<<(B_*P_ + 255)/256, 256>>>();
    }

    img_max<<<B_, 256>>>();
    final_kernel<<<1, 64>>>(cls, out);
    pixel_kernel<<<(B_*HOUT*WOUT + 255)/256, 256>>>(out + 8);
}